// round 1
// baseline (speedup 1.0000x reference)
#include <cuda_runtime.h>

// Problem constants (fixed shapes from reference setup_inputs)
#define LNM   19
#define BSZ   2
#define HH    800
#define WW    640
#define HW    (HH * WW)            // 512000
#define NPAIR (BSZ * LNM)          // 38
#define NCHUNK 32
#define TPB   256
#define F4_PER_PLANE (HW / 4)          // 128000
#define F4_PER_CHUNK (F4_PER_PLANE / NCHUNK) // 4000
#define R1SQ  1681.0f              // 41*41
#define INV_R2 (1.0f / 41.0f)

// Scratch for per-(pair,chunk) partial sums: [pair][chunk][4] = {bce, l1x, l1y, msum}
__device__ float g_partial[NPAIR * NCHUNK * 4];

__global__ __launch_bounds__(TPB) void loss_main_kernel(
    const float* __restrict__ fm,   // (B, 3L, H, W)
    const float* __restrict__ lmk)  // (B, L, 2)
{
    const int pair  = blockIdx.y;           // 0..37
    const int chunk = blockIdx.x;           // 0..31
    const int b = pair / LNM;
    const int l = pair % LNM;

    // Landmark center (round-half-to-even to match jnp.round)
    const float X = rintf(lmk[(b * LNM + l) * 2 + 0] * (float)(HH - 1));
    const float Y = rintf(lmk[(b * LNM + l) * 2 + 1] * (float)(WW - 1));

    // Channel base pointers as float4 streams
    const float4* __restrict__ lg =
        (const float4*)(fm + ((size_t)b * 3 * LNM + l) * (size_t)HW);
    const float4* __restrict__ px = lg + (size_t)LNM * F4_PER_PLANE;
    const float4* __restrict__ py = px + (size_t)LNM * F4_PER_PLANE;

    float s_bce = 0.0f, s_x = 0.0f, s_y = 0.0f, s_m = 0.0f;

    const int start = chunk * F4_PER_CHUNK;
    const int end   = start + F4_PER_CHUNK;

    for (int p4 = start + threadIdx.x; p4 < end; p4 += TPB) {
        const int h = p4 / (WW / 4);
        const int w = (p4 - h * (WW / 4)) * 4;

        const float dx   = X - (float)h;
        const float dx2  = dx * dx;
        const float offx = dx * INV_R2;

        const float4 x4  = __ldg(&lg[p4]);
        const float4 px4 = __ldg(&px[p4]);
        const float4 py4 = __ldg(&py[p4]);

        const float xs[4]  = {x4.x,  x4.y,  x4.z,  x4.w};
        const float pxs[4] = {px4.x, px4.y, px4.z, px4.w};
        const float pys[4] = {py4.x, py4.y, py4.z, py4.w};

        #pragma unroll
        for (int k = 0; k < 4; ++k) {
            const float dy   = Y - (float)(w + k);
            const float r2   = fmaf(dy, dy, dx2);
            const float heat = (r2 <= R1SQ) ? 1.0f : 0.0f;

            // BCE-with-logits: softplus(x) - x*heat
            const float x  = xs[k];
            const float sp = fmaxf(x, 0.0f) + __logf(1.0f + __expf(-fabsf(x)));
            s_bce += sp - x * heat;

            // Masked L1 for offsets
            const float vx = fabsf(pxs[k] - offx);
            const float vy = fabsf(pys[k] - dy * INV_R2);
            s_x = fmaf(heat, vx, s_x);
            s_y = fmaf(heat, vy, s_y);
            s_m += heat;
        }
    }

    // Block reduction of 4 accumulators (warp shuffle + smem)
    const unsigned FULL = 0xFFFFFFFFu;
    #pragma unroll
    for (int off = 16; off > 0; off >>= 1) {
        s_bce += __shfl_down_sync(FULL, s_bce, off);
        s_x   += __shfl_down_sync(FULL, s_x,   off);
        s_y   += __shfl_down_sync(FULL, s_y,   off);
        s_m   += __shfl_down_sync(FULL, s_m,   off);
    }

    __shared__ float smem[4][TPB / 32];
    const int lane = threadIdx.x & 31;
    const int wid  = threadIdx.x >> 5;
    if (lane == 0) {
        smem[0][wid] = s_bce;
        smem[1][wid] = s_x;
        smem[2][wid] = s_y;
        smem[3][wid] = s_m;
    }
    __syncthreads();

    if (wid == 0) {
        float v0 = (lane < TPB / 32) ? smem[0][lane] : 0.0f;
        float v1 = (lane < TPB / 32) ? smem[1][lane] : 0.0f;
        float v2 = (lane < TPB / 32) ? smem[2][lane] : 0.0f;
        float v3 = (lane < TPB / 32) ? smem[3][lane] : 0.0f;
        #pragma unroll
        for (int off = 4; off > 0; off >>= 1) {
            v0 += __shfl_down_sync(FULL, v0, off);
            v1 += __shfl_down_sync(FULL, v1, off);
            v2 += __shfl_down_sync(FULL, v2, off);
            v3 += __shfl_down_sync(FULL, v3, off);
        }
        if (lane == 0) {
            float* dst = &g_partial[(pair * NCHUNK + chunk) * 4];
            dst[0] = v0;
            dst[1] = v1;
            dst[2] = v2;
            dst[3] = v3;
        }
    }
}

__global__ void loss_final_kernel(float* __restrict__ out)
{
    __shared__ float red[64];
    const int t = threadIdx.x;

    float pl = 0.0f;
    if (t < NPAIR) {
        float sb = 0.0f, sx = 0.0f, sy = 0.0f, sm = 0.0f;
        #pragma unroll 4
        for (int c = 0; c < NCHUNK; ++c) {
            const float* p = &g_partial[(t * NCHUNK + c) * 4];
            sb += p[0];
            sx += p[1];
            sy += p[2];
            sm += p[3];
        }
        pl = 2.0f * sb / (float)HW + sx / sm + sy / sm;
    }
    red[t] = pl;
    __syncthreads();
    #pragma unroll
    for (int s = 32; s > 0; s >>= 1) {
        if (t < s) red[t] += red[t + s];
        __syncthreads();
    }
    if (t == 0) out[0] = red[0] / (float)NPAIR;
}

extern "C" void kernel_launch(void* const* d_in, const int* in_sizes, int n_in,
                              void* d_out, int out_size)
{
    const float* fm  = (const float*)d_in[0];
    const float* lmk = (const float*)d_in[1];
    float* out = (float*)d_out;

    dim3 grid(NCHUNK, NPAIR);
    loss_main_kernel<<<grid, TPB>>>(fm, lmk);
    loss_final_kernel<<<1, 64>>>(out);
}